// round 4
// baseline (speedup 1.0000x reference)
#include <cuda_runtime.h>
#include <cuda_bf16.h>
#include <math.h>
#include <stdint.h>

// ContrastiveLoss via int8 IMMA (mma.sync.m16n8k32.s8 — 2x MACs/instr vs bf16).
// loss = log(S_A_up + S_C_up + S_B_full + sim_s) - log(sim_s)
//   A=UU^T, C=VV^T, B=UV^T on L2-normalized halves; per-row symmetric int8
//   quantization: q = rint(v*127/max|v|), cos = s_i*s_j*(q_i.q_j).
//   sim_s = sum exp(diag(B)/2) in exact fp32 from original x.
//
// g_xq: 64 bands of 128 rows; band = 2 K-blocks (k 0..127 / 128..255);
// K-block = 128 rows x 128B, SW128-swizzled, 16KB contiguous. Band=32KB.

#define D      256
#define NROWS  8192
#define NHALF  4096
#define NT     32
#define BAND_BYTES 32768
#define KBLK_BYTES 16384
#define SMEM_DATA   2048
#define SMEM_TOTAL  (SMEM_DATA + 4 * KBLK_BYTES)   // 67584

#define MB_K0   16
#define MB_K1   24
#define SC_A    512            // sA[128] floats
#define SC_B    1024           // sB[128] floats

__device__ __align__(128) uint8_t g_xq[NROWS * D];   // 2 MB int8 swizzled
__device__ float  g_scl[NROWS];    // s = max|v|*inv/127
__device__ float  g_inv[NROWS];
__device__ double g_main;
__device__ double g_sims;

// ---------------------------------------------------------------------------
static __device__ __forceinline__ uint32_t smem_u32(const void* p) {
    uint32_t a;
    asm("{ .reg .u64 t; cvta.to.shared.u64 t, %1; cvt.u32.u64 %0, t; }"
        : "=r"(a) : "l"(p));
    return a;
}

#define MBAR_INIT(addr, cnt) \
    asm volatile("mbarrier.init.shared.b64 [%0], %1;" :: "r"(addr), "r"(cnt) : "memory")

#define MBAR_EXPECT_TX(addr, bytes) \
    asm volatile("mbarrier.arrive.expect_tx.shared.b64 _, [%0], %1;" \
                 :: "r"(addr), "r"(bytes) : "memory")

#define MBAR_WAIT(addr, parity) do {                                          \
    uint32_t _m = (addr); uint32_t _p = (parity); uint32_t _done;             \
    asm volatile("{\n\t.reg .pred p;\n\t"                                     \
        "mbarrier.try_wait.parity.acquire.cta.shared::cta.b64 p, [%1], %2;\n\t"\
        "selp.b32 %0, 1, 0, p;\n\t}"                                          \
        : "=r"(_done) : "r"(_m), "r"(_p) : "memory");                         \
    if (!_done) {                                                             \
        asm volatile("{\n\t.reg .pred P1;\n\t"                                \
            "W_%=:\n\t"                                                       \
            "mbarrier.try_wait.parity.acquire.cta.shared::cta.b64 P1, [%0], %1, 0x989680;\n\t" \
            "@P1 bra.uni WD_%=;\n\t"                                          \
            "bra.uni W_%=;\n\t"                                               \
            "WD_%=:\n\t}" :: "r"(_m), "r"(_p) : "memory");                    \
    }                                                                         \
} while (0)

#define BULK_G2S(dst, src, bytes, mbar) \
    asm volatile("cp.async.bulk.shared::cta.global.mbarrier::complete_tx::bytes [%0], [%1], %2, [%3];" \
                 :: "r"(dst), "l"(src), "r"(bytes), "r"(mbar) : "memory")

static __device__ __forceinline__ void ldsm_x4(uint32_t* r, uint32_t addr) {
    asm volatile("ldmatrix.sync.aligned.m8n8.x4.shared.b16 {%0,%1,%2,%3}, [%4];"
                 : "=r"(r[0]), "=r"(r[1]), "=r"(r[2]), "=r"(r[3]) : "r"(addr));
}

static __device__ __forceinline__ void imma16832(int32_t* d, const uint32_t* a,
                                                 uint32_t b0, uint32_t b1) {
    asm volatile("mma.sync.aligned.m16n8k32.row.col.s32.s8.s8.s32 "
                 "{%0,%1,%2,%3}, {%4,%5,%6,%7}, {%8,%9}, {%0,%1,%2,%3};"
                 : "+r"(d[0]), "+r"(d[1]), "+r"(d[2]), "+r"(d[3])
                 : "r"(a[0]), "r"(a[1]), "r"(a[2]), "r"(a[3]), "r"(b0), "r"(b1));
}

static __device__ __forceinline__ uint32_t sw128(uint32_t off) {
    return off ^ ((off >> 3) & 0x70);
}

// ---------------------------------------------------------------------------
// Per row: L2 norm, max|v|, int8 quantize into swizzled band layout.
// Block 0 also zeroes the global accumulators (stream-ordered before use).
__global__ __launch_bounds__(256) void normalize_k(const float* __restrict__ x) {
    const int row = blockIdx.x;
    const int t   = threadIdx.x;
    if (row == 0 && t == 0) { g_main = 0.0; g_sims = 0.0; }

    float v  = x[row * D + t];
    float ss = v * v;
    float mx = fabsf(v);
    #pragma unroll
    for (int o = 16; o > 0; o >>= 1) {
        ss += __shfl_xor_sync(0xFFFFFFFFu, ss, o);
        mx = fmaxf(mx, __shfl_xor_sync(0xFFFFFFFFu, mx, o));
    }
    __shared__ float rs[8], rm[8];
    if ((t & 31) == 0) { rs[t >> 5] = ss; rm[t >> 5] = mx; }
    __syncthreads();
    float tss = 0.0f, tmx = 0.0f;
    #pragma unroll
    for (int i = 0; i < 8; i++) { tss += rs[i]; tmx = fmaxf(tmx, rm[i]); }

    float inv = 1.0f / fmaxf(sqrtf(tss), 1e-8f);
    if (t == 0) {
        g_inv[row] = inv;
        g_scl[row] = tmx * inv * (1.0f / 127.0f);
    }

    int q = __float2int_rn(v * (127.0f / tmx));
    int band = row >> 7, rib = row & 127;
    int kb = t >> 7;
    uint32_t off = sw128((uint32_t)(rib * 128 + (t & 127)));
    g_xq[(size_t)band * BAND_BYTES + (size_t)kb * KBLK_BYTES + off] = (uint8_t)(int8_t)q;
}

// Exact fp32 diagonal of B: sim_s
__global__ __launch_bounds__(256) void diag_k(const float* __restrict__ x) {
    const int row = blockIdx.x;
    const int t   = threadIdx.x;
    float a = x[row * D + t];
    float b = x[(NHALF + row) * D + t];
    float s = a * b;
    #pragma unroll
    for (int o = 16; o > 0; o >>= 1) s += __shfl_xor_sync(0xFFFFFFFFu, s, o);
    __shared__ float red[8];
    if ((t & 31) == 0) red[t >> 5] = s;
    __syncthreads();
    if (t == 0) {
        float d2 = 0.0f;
        #pragma unroll
        for (int i = 0; i < 8; i++) d2 += red[i];
        float c = d2 * g_inv[row] * g_inv[NHALF + row];
        atomicAdd(&g_sims, (double)__expf(0.5f * c));
    }
}

// ---------------------------------------------------------------------------
// One CTA = one 128x128x256 int8 tile. 1024 B-full + 528 A-up + 528 C-up.
__global__ __launch_bounds__(256, 2) void tile_k() {
    extern __shared__ __align__(1024) uint8_t smem[];
    uint32_t sb = smem_u32(smem);
    const int tid  = threadIdx.x;
    const int wid  = tid >> 5;
    const int lane = tid & 31;

    // ---- tile decode ----
    int t = blockIdx.x;
    int bi, bj;
    bool maskt = false;
    const uint8_t *gA, *gB;
    if (t < 1024) {
        bi = t >> 5; bj = t & 31;
        gA = g_xq + (size_t)bi * BAND_BYTES;
        gB = g_xq + (size_t)(32 + bj) * BAND_BYTES;
    } else {
        t -= 1024;
        int m = (t >= 528) ? 1 : 0;
        int u = t - m * 528;
        int b_ = 0;
        while (u >= NT - b_) { u -= NT - b_; b_++; }
        bi = b_; bj = b_ + u;
        maskt = (bi == bj);
        gA = g_xq + (size_t)(m * 32 + bi) * BAND_BYTES;
        gB = g_xq + (size_t)(m * 32 + bj) * BAND_BYTES;
    }
    const int row0 = bi << 7;
    const int col0 = bj << 7;

    // ---- scales into smem (visible after the syncthreads below) ----
    if (tid < 128)
        *(float*)(smem + SC_A + tid * 4) = g_scl[row0 + tid];
    else
        *(float*)(smem + SC_B + (tid - 128) * 4) = g_scl[col0 + (tid - 128)];

    if (tid == 0) { MBAR_INIT(sb + MB_K0, 1); MBAR_INIT(sb + MB_K1, 1); }
    __syncthreads();

    const uint32_t dA = sb + SMEM_DATA;           // A: 2 K-blocks, 32KB
    const uint32_t dB = dA + 2 * KBLK_BYTES;      // B: 2 K-blocks, 32KB
    if (tid == 0) {
        MBAR_EXPECT_TX(sb + MB_K0, 2 * KBLK_BYTES);
        BULK_G2S(dA,              gA,              KBLK_BYTES, sb + MB_K0);
        BULK_G2S(dB,              gB,              KBLK_BYTES, sb + MB_K0);
        MBAR_EXPECT_TX(sb + MB_K1, 2 * KBLK_BYTES);
        BULK_G2S(dA + KBLK_BYTES, gA + KBLK_BYTES, KBLK_BYTES, sb + MB_K1);
        BULK_G2S(dB + KBLK_BYTES, gB + KBLK_BYTES, KBLK_BYTES, sb + MB_K1);
    }

    // ---- per-lane ldmatrix geometry ----
    const int warp_m = wid & 3;          // 32-row strip
    const int warp_n = wid >> 2;         // 64-col strip
    const int g      = lane >> 3;
    const uint32_t sw = (uint32_t)((lane & 7) << 4);

    // A: tiles (g&1 -> row half, g>>1 -> k half)
    uint32_t aRow[2];
    const uint32_t aKh = (uint32_t)((g >> 1) * 16);
    #pragma unroll
    for (int am = 0; am < 2; am++) {
        int r = warp_m * 32 + am * 16 + (g & 1) * 8 + (lane & 7);
        aRow[am] = (uint32_t)(r * 128);
    }
    // B: tiles (g>>1 -> col half, g&1 -> k half)
    uint32_t bRow[4];
    const uint32_t bKh = (uint32_t)((g & 1) * 16);
    #pragma unroll
    for (int bg = 0; bg < 4; bg++) {
        int r = warp_n * 64 + bg * 16 + (g >> 1) * 8 + (lane & 7);
        bRow[bg] = (uint32_t)(r * 128);
    }

    int32_t d[2][8][4];
    #pragma unroll
    for (int i = 0; i < 2; i++)
        #pragma unroll
        for (int j = 0; j < 8; j++)
            #pragma unroll
            for (int k = 0; k < 4; k++) d[i][j][k] = 0;

    // ---- mainloop: 8 k32-steps, no mid-loop sync besides two waits ----
    #pragma unroll
    for (int s = 0; s < 8; s++) {
        if (s == 0) MBAR_WAIT(sb + MB_K0, 0u);
        if (s == 4) MBAR_WAIT(sb + MB_K1, 0u);
        const uint32_t kblk = (uint32_t)((s >> 2) * KBLK_BYTES);
        const uint32_t kc   = (uint32_t)((s & 3) * 32);

        uint32_t a[2][4], b[4][4];
        #pragma unroll
        for (int am = 0; am < 2; am++)
            ldsm_x4(a[am], dA + kblk + aRow[am] + ((kc + aKh) ^ sw));
        #pragma unroll
        for (int bg = 0; bg < 4; bg++)
            ldsm_x4(b[bg], dB + kblk + bRow[bg] + ((kc + bKh) ^ sw));

        #pragma unroll
        for (int am = 0; am < 2; am++)
            #pragma unroll
            for (int bg = 0; bg < 4; bg++) {
                imma16832(d[am][bg * 2 + 0], a[am], b[bg][0], b[bg][1]);
                imma16832(d[am][bg * 2 + 1], a[am], b[bg][2], b[bg][3]);
            }
    }

    // ---- epilogue: scale -> exp -> mask -> reduce ----
    const int rbase = warp_m * 32 + (lane >> 2);
    const int cbase = warp_n * 64 + 2 * (lane & 3);
    const float* sA = (const float*)(smem + SC_A);
    const float* sB = (const float*)(smem + SC_B);

    float cs[16];
    #pragma unroll
    for (int bn = 0; bn < 8; bn++) {
        cs[bn * 2 + 0] = sB[cbase + bn * 8 + 0];
        cs[bn * 2 + 1] = sB[cbase + bn * 8 + 1];
    }

    float sum = 0.0f;
    #pragma unroll
    for (int am = 0; am < 2; am++) {
        #pragma unroll
        for (int kk = 0; kk < 2; kk++) {
            const int lrow = rbase + am * 16 + kk * 8;
            const float rsc = 0.5f * sA[lrow];
            #pragma unroll
            for (int bn = 0; bn < 8; bn++) {
                #pragma unroll
                for (int k1 = 0; k1 < 2; k1++) {
                    float fd = (float)d[am][bn][kk * 2 + k1];
                    float e = __expf(fd * (rsc * cs[bn * 2 + k1]));
                    if (maskt) {
                        int col = cbase + bn * 8 + k1;
                        if (col < lrow) e = 0.0f;
                    }
                    sum += e;
                }
            }
        }
    }

    #pragma unroll
    for (int o = 16; o > 0; o >>= 1)
        sum += __shfl_xor_sync(0xFFFFFFFFu, sum, o);

    __shared__ float wsum[8];
    if (lane == 0) wsum[wid] = sum;
    __syncthreads();
    if (tid == 0) {
        float s = 0.0f;
        #pragma unroll
        for (int i = 0; i < 8; i++) s += wsum[i];
        atomicAdd(&g_main, (double)s);
    }
}

// ---------------------------------------------------------------------------
__global__ void fin_k(float* __restrict__ out) {
    double sim_all = g_main + g_sims;
    out[0] = (float)(log(sim_all) - log(g_sims));
}

extern "C" void kernel_launch(void* const* d_in, const int* in_sizes, int n_in,
                              void* d_out, int out_size) {
    const float* x = (const float*)d_in[0];
    float* out = (float*)d_out;

    cudaFuncSetAttribute(tile_k, cudaFuncAttributeMaxDynamicSharedMemorySize, SMEM_TOTAL);

    normalize_k<<<NROWS, 256>>>(x);
    diag_k<<<NHALF, 256>>>(x);
    tile_k<<<1024 + 2 * 528, 256, SMEM_TOTAL>>>();
    fin_k<<<1, 1>>>(out);
}

// round 5
// speedup vs baseline: 2.6476x; 2.6476x over previous
#include <cuda_runtime.h>
#include <cuda_bf16.h>
#include <math.h>
#include <stdint.h>

// ContrastiveLoss via warp-level bf16 mma.sync (HMMA).
// loss = log(S_A_up + S_C_up + S_B_full + sim_s) - log(sim_s)
//   A=UU^T, C=VV^T, B=UV^T on L2-normalized halves.
//   sim_s = sum exp(diag(B)/2), harvested from the 32 diagonal B tiles.
//
// g_xb: 64 bands of 128 rows; band = 4 K-blocks of 64 bf16 = 128 rows x 128B,
// SW128-swizzled, 16KB contiguous -> cp.async.bulk feeds MMA smem directly.

#define D      256
#define NROWS  8192
#define NHALF  4096
#define NT     32
#define BAND_BYTES 65536
#define KBLK_BYTES 16384
#define STAGE_BYTES 32768              // A 16KB + B 16KB
#define SMEM_DATA   1024
#define SMEM_TOTAL  (SMEM_DATA + 2 * STAGE_BYTES)   // 66560

#define MB_FULL0  16
#define MB_FULL1  24
#define MB_EMPTY0 32
#define MB_EMPTY1 40

__device__ __align__(128) uint8_t g_xb[NROWS * D * 2];   // 4 MB bf16 swizzled
__device__ double g_main;
__device__ double g_sims;

// ---------------------------------------------------------------------------
static __device__ __forceinline__ uint32_t smem_u32(const void* p) {
    uint32_t a;
    asm("{ .reg .u64 t; cvta.to.shared.u64 t, %1; cvt.u32.u64 %0, t; }"
        : "=r"(a) : "l"(p));
    return a;
}

static __device__ __forceinline__ float ex2f(float x) {
    float y;
    asm("ex2.approx.f32 %0, %1;" : "=f"(y) : "f"(x));
    return y;
}
#define EXP_HALF_LOG2E 0.7213475204444817f   // 0.5 * log2(e)

#define MBAR_INIT(addr, cnt) \
    asm volatile("mbarrier.init.shared.b64 [%0], %1;" :: "r"(addr), "r"(cnt) : "memory")

#define MBAR_ARRIVE(addr) \
    asm volatile("mbarrier.arrive.shared.b64 _, [%0];" :: "r"(addr) : "memory")

#define MBAR_EXPECT_TX(addr, bytes) \
    asm volatile("mbarrier.arrive.expect_tx.shared.b64 _, [%0], %1;" \
                 :: "r"(addr), "r"(bytes) : "memory")

#define MBAR_WAIT(addr, parity) do {                                          \
    uint32_t _m = (addr); uint32_t _p = (parity); uint32_t _done;             \
    asm volatile("{\n\t.reg .pred p;\n\t"                                     \
        "mbarrier.try_wait.parity.acquire.cta.shared::cta.b64 p, [%1], %2;\n\t"\
        "selp.b32 %0, 1, 0, p;\n\t}"                                          \
        : "=r"(_done) : "r"(_m), "r"(_p) : "memory");                         \
    if (!_done) {                                                             \
        asm volatile("{\n\t.reg .pred P1;\n\t"                                \
            "W_%=:\n\t"                                                       \
            "mbarrier.try_wait.parity.acquire.cta.shared::cta.b64 P1, [%0], %1, 0x989680;\n\t" \
            "@P1 bra.uni WD_%=;\n\t"                                          \
            "bra.uni W_%=;\n\t"                                               \
            "WD_%=:\n\t}" :: "r"(_m), "r"(_p) : "memory");                    \
    }                                                                         \
} while (0)

#define BULK_G2S(dst, src, bytes, mbar) \
    asm volatile("cp.async.bulk.shared::cta.global.mbarrier::complete_tx::bytes [%0], [%1], %2, [%3];" \
                 :: "r"(dst), "l"(src), "r"(bytes), "r"(mbar) : "memory")

static __device__ __forceinline__ void ldsm_x4(uint32_t* r, uint32_t addr) {
    asm volatile("ldmatrix.sync.aligned.m8n8.x4.shared.b16 {%0,%1,%2,%3}, [%4];"
                 : "=r"(r[0]), "=r"(r[1]), "=r"(r[2]), "=r"(r[3]) : "r"(addr));
}

static __device__ __forceinline__ void mma16816(float* d, const uint32_t* a,
                                                uint32_t b0, uint32_t b1) {
    asm volatile("mma.sync.aligned.m16n8k16.row.col.f32.bf16.bf16.f32 "
                 "{%0,%1,%2,%3}, {%4,%5,%6,%7}, {%8,%9}, {%0,%1,%2,%3};"
                 : "+f"(d[0]), "+f"(d[1]), "+f"(d[2]), "+f"(d[3])
                 : "r"(a[0]), "r"(a[1]), "r"(a[2]), "r"(a[3]), "r"(b0), "r"(b1));
}

// ---------------------------------------------------------------------------
// Warp per row: L2 norm -> bf16 normalized row into swizzled band layout.
// Block 0 also zeroes global accumulators (stream-ordered before tile_k).
__global__ __launch_bounds__(256) void normalize_k(const float* __restrict__ x) {
    const int tid  = threadIdx.x;
    const int wid  = tid >> 5;
    const int lane = tid & 31;
    const int row  = blockIdx.x * 8 + wid;
    if (blockIdx.x == 0 && tid == 0) { g_main = 0.0; g_sims = 0.0; }

    const float4* xr = (const float4*)(x + row * D);
    float4 v0 = xr[lane * 2 + 0];
    float4 v1 = xr[lane * 2 + 1];

    float ss = v0.x * v0.x + v0.y * v0.y + v0.z * v0.z + v0.w * v0.w
             + v1.x * v1.x + v1.y * v1.y + v1.z * v1.z + v1.w * v1.w;
    #pragma unroll
    for (int o = 16; o > 0; o >>= 1) ss += __shfl_xor_sync(0xFFFFFFFFu, ss, o);
    float inv = 1.0f / fmaxf(sqrtf(ss), 1e-8f);

    uint32_t p[4];
    p[0] = (uint32_t)__bfloat16_as_ushort(__float2bfloat16(v0.x * inv))
         | ((uint32_t)__bfloat16_as_ushort(__float2bfloat16(v0.y * inv)) << 16);
    p[1] = (uint32_t)__bfloat16_as_ushort(__float2bfloat16(v0.z * inv))
         | ((uint32_t)__bfloat16_as_ushort(__float2bfloat16(v0.w * inv)) << 16);
    p[2] = (uint32_t)__bfloat16_as_ushort(__float2bfloat16(v1.x * inv))
         | ((uint32_t)__bfloat16_as_ushort(__float2bfloat16(v1.y * inv)) << 16);
    p[3] = (uint32_t)__bfloat16_as_ushort(__float2bfloat16(v1.z * inv))
         | ((uint32_t)__bfloat16_as_ushort(__float2bfloat16(v1.w * inv)) << 16);

    // lane covers k = lane*8 .. lane*8+7 -> 16 contiguous bytes, 16B-aligned.
    int band = row >> 7, rib = row & 127;
    int kb = lane >> 3;                                   // K-block (64 k each)
    uint32_t off = (uint32_t)(rib * 128 + (lane & 7) * 16);
    off ^= (off >> 3) & 0x70;                             // SW128
    *(uint4*)(g_xb + (size_t)band * BAND_BYTES + (size_t)kb * KBLK_BYTES + off)
        = *(uint4*)p;
}

// ---------------------------------------------------------------------------
// One CTA = one 128x128x256 tile. 1024 B-full + 528 A-upper + 528 C-upper.
__global__ __launch_bounds__(256, 2) void tile_k() {
    extern __shared__ __align__(1024) uint8_t smem[];
    uint32_t sb = smem_u32(smem);
    const int tid  = threadIdx.x;
    const int wid  = tid >> 5;
    const int lane = tid & 31;

    // ---- tile decode ----
    int t = blockIdx.x;
    int bi, bj;
    bool maskt = false, bdiag = false;
    const uint8_t *gA, *gB;
    if (t < 1024) {                       // B = U V^T, full
        bi = t >> 5; bj = t & 31;
        bdiag = (bi == bj);               // carries diag(B) -> sim_s
        gA = g_xb + (size_t)bi * BAND_BYTES;
        gB = g_xb + (size_t)(32 + bj) * BAND_BYTES;
    } else {                              // A (m=0) / C (m=1), upper
        t -= 1024;
        int m = (t >= 528) ? 1 : 0;
        int u = t - m * 528;
        int b_ = 0;
        while (u >= NT - b_) { u -= NT - b_; b_++; }
        bi = b_; bj = b_ + u;
        maskt = (bi == bj);
        gA = g_xb + (size_t)(m * 32 + bi) * BAND_BYTES;
        gB = g_xb + (size_t)(m * 32 + bj) * BAND_BYTES;
    }

    if (tid == 0) {
        MBAR_INIT(sb + MB_FULL0, 1);  MBAR_INIT(sb + MB_FULL1, 1);
        MBAR_INIT(sb + MB_EMPTY0, 8); MBAR_INIT(sb + MB_EMPTY1, 8);
    }
    __syncthreads();

    if (tid == 0) {
        #pragma unroll
        for (int s = 0; s < 2; s++) {
            uint32_t stb = sb + SMEM_DATA + s * STAGE_BYTES;
            uint32_t fb  = sb + MB_FULL0 + 8 * s;
            MBAR_EXPECT_TX(fb, (uint32_t)STAGE_BYTES);
            BULK_G2S(stb,         gA + s * KBLK_BYTES, KBLK_BYTES, fb);
            BULK_G2S(stb + 16384, gB + s * KBLK_BYTES, KBLK_BYTES, fb);
        }
    }

    // ---- per-warp / per-lane ldmatrix geometry (verified in R3) ----
    const int warp_m = wid & 3;          // 32-row strip
    const int warp_n = wid >> 2;         // 64-col strip
    const int lrow = lane & 15;
    const uint32_t xoff = ((lane >> 4) & 1) * 16;

    uint32_t aRow[2], aSw[2], bRow[4], bSw[4];
    #pragma unroll
    for (int am = 0; am < 2; am++) {
        int r = warp_m * 32 + am * 16 + lrow;
        aRow[am] = (uint32_t)(r * 128);
        aSw[am]  = (uint32_t)((r & 7) << 4);
    }
    #pragma unroll
    for (int bg = 0; bg < 4; bg++) {
        int r = warp_n * 64 + bg * 16 + lrow;
        bRow[bg] = (uint32_t)(r * 128);
        bSw[bg]  = (uint32_t)((r & 7) << 4);
    }

    float d[2][8][4];
    #pragma unroll
    for (int i = 0; i < 2; i++)
        #pragma unroll
        for (int j = 0; j < 8; j++)
            #pragma unroll
            for (int k = 0; k < 4; k++) d[i][j][k] = 0.0f;

    // ---- chunk loop: 4 chunks of K=64, double-buffered ----
    #pragma unroll
    for (int c = 0; c < 4; c++) {
        const int st = c & 1;
        const uint32_t stA = sb + SMEM_DATA + st * STAGE_BYTES;
        const uint32_t stB = stA + 16384;
        MBAR_WAIT(sb + MB_FULL0 + 8 * st, (uint32_t)((c >> 1) & 1));

        #pragma unroll
        for (int ks = 0; ks < 4; ks++) {
            const uint32_t kc = (uint32_t)(ks * 32);
            uint32_t a[2][4], b[4][4];
            #pragma unroll
            for (int am = 0; am < 2; am++)
                ldsm_x4(a[am], stA + aRow[am] + ((kc + xoff) ^ aSw[am]));
            #pragma unroll
            for (int bg = 0; bg < 4; bg++)
                ldsm_x4(b[bg], stB + bRow[bg] + ((kc + xoff) ^ bSw[bg]));

            #pragma unroll
            for (int am = 0; am < 2; am++)
                #pragma unroll
                for (int bg = 0; bg < 4; bg++) {
                    mma16816(d[am][bg * 2 + 0], a[am], b[bg][0], b[bg][2]);
                    mma16816(d[am][bg * 2 + 1], a[am], b[bg][1], b[bg][3]);
                }
        }

        if (lane == 0) MBAR_ARRIVE(sb + MB_EMPTY0 + 8 * st);
        if (tid == 0 && c < 2) {
            MBAR_WAIT(sb + MB_EMPTY0 + 8 * st, 0u);
            uint32_t fb = sb + MB_FULL0 + 8 * st;
            MBAR_EXPECT_TX(fb, (uint32_t)STAGE_BYTES);
            BULK_G2S(stA, gA + (c + 2) * KBLK_BYTES, KBLK_BYTES, fb);
            BULK_G2S(stB, gB + (c + 2) * KBLK_BYTES, KBLK_BYTES, fb);
        }
    }

    // ---- epilogue: exp2(d * 0.5*log2 e) -> reduce; uniform tile-type branch ----
    const int rbase = warp_m * 32 + (lane >> 2);
    const int cbase = warp_n * 64 + 2 * (lane & 3);
    float sum = 0.0f;
    float sumd = 0.0f;

    if (!maskt && !bdiag) {
        #pragma unroll
        for (int am = 0; am < 2; am++)
            #pragma unroll
            for (int bn = 0; bn < 8; bn++)
                #pragma unroll
                for (int k = 0; k < 4; k++)
                    sum += ex2f(d[am][bn][k] * EXP_HALF_LOG2E);
    } else if (maskt) {
        #pragma unroll
        for (int am = 0; am < 2; am++)
            #pragma unroll
            for (int bn = 0; bn < 8; bn++)
                #pragma unroll
                for (int k = 0; k < 4; k++) {
                    float e = ex2f(d[am][bn][k] * EXP_HALF_LOG2E);
                    int row = rbase + am * 16 + ((k >> 1) << 3);
                    int col = cbase + bn * 8 + (k & 1);
                    sum += (col >= row) ? e : 0.0f;
                }
    } else {  // bdiag: full sum + harvest diagonal into sim_s
        #pragma unroll
        for (int am = 0; am < 2; am++)
            #pragma unroll
            for (int bn = 0; bn < 8; bn++)
                #pragma unroll
                for (int k = 0; k < 4; k++) {
                    float e = ex2f(d[am][bn][k] * EXP_HALF_LOG2E);
                    int row = rbase + am * 16 + ((k >> 1) << 3);
                    int col = cbase + bn * 8 + (k & 1);
                    sum += e;
                    if (row == col) sumd += e;
                }
    }

    #pragma unroll
    for (int o = 16; o > 0; o >>= 1)
        sum += __shfl_xor_sync(0xFFFFFFFFu, sum, o);

    __shared__ float wsum[8];
    if (lane == 0) wsum[wid] = sum;

    if (bdiag) {
        #pragma unroll
        for (int o = 16; o > 0; o >>= 1)
            sumd += __shfl_xor_sync(0xFFFFFFFFu, sumd, o);
        __shared__ float wsumd[8];
        if (lane == 0) wsumd[wid] = sumd;
        __syncthreads();
        if (tid == 0) {
            float s = 0.0f, sd = 0.0f;
            #pragma unroll
            for (int i = 0; i < 8; i++) { s += wsum[i]; sd += wsumd[i]; }
            atomicAdd(&g_main, (double)s);
            atomicAdd(&g_sims, (double)sd);
        }
    } else {
        __syncthreads();
        if (tid == 0) {
            float s = 0.0f;
            #pragma unroll
            for (int i = 0; i < 8; i++) s += wsum[i];
            atomicAdd(&g_main, (double)s);
        }
    }
}

// ---------------------------------------------------------------------------
__global__ void fin_k(float* __restrict__ out) {
    double sim_all = g_main + g_sims;
    out[0] = (float)(log(sim_all) - log(g_sims));
}

extern "C" void kernel_launch(void* const* d_in, const int* in_sizes, int n_in,
                              void* d_out, int out_size) {
    const float* x = (const float*)d_in[0];
    float* out = (float*)d_out;

    cudaFuncSetAttribute(tile_k, cudaFuncAttributeMaxDynamicSharedMemorySize, SMEM_TOTAL);

    normalize_k<<<NROWS / 8, 256>>>(x);
    tile_k<<<1024 + 2 * 528, 256, SMEM_TOTAL>>>();
    fin_k<<<1, 1>>>(out);
}